// round 17
// baseline (speedup 1.0000x reference)
#include <cuda_runtime.h>
#include <math.h>

// Problem constants
#define BB 256
#define TT 1000
#define NN 200
#define NII 7

#define ALPHA_F 0.2f
#define OMA_F   0.8f
#define NSC_F   0.0948683292f   // 0.15*sqrt(2*0.2)

typedef unsigned long long u64;

// packed fp32x2 FMA, operands pre-packed in b64 (no operand MOVs)
__device__ __forceinline__ void ffma2(u64& acc, u64 w, u64 y) {
    asm("fma.rn.f32x2 %0, %1, %2, %0;" : "+l"(acc) : "l"(w), "l"(y));
}
__device__ __forceinline__ u64 add2(u64 a, u64 b) {
    u64 s; asm("add.rn.f32x2 %0, %1, %2;" : "=l"(s) : "l"(a), "l"(b));
    return s;
}
__device__ __forceinline__ float hsum8(u64 a, u64 b, u64 c, u64 d) {
    u64 s = add2(add2(a, b), add2(c, d));
    float2 f;
    asm("mov.b64 {%0, %1}, %2;" : "=f"(f.x), "=f"(f.y) : "l"(s));
    return f.x + f.y;
}

// ONE batch row per CTA. 256 CTAs run as ~2 waves on 148 SMs; per-step
// instruction count per warp is halved vs the 2-row version, and ~20
// freed registers give ptxas real scheduling slack on the LDS chain.
__global__ void __launch_bounds__(256, 1)
rnn_1row_kernel(const float* __restrict__ y0,
                const float* __restrict__ u_seq,
                const float* __restrict__ noise,
                const float* __restrict__ W_in_raw,
                const float* __restrict__ W_rec,
                const float* __restrict__ b_rec,
                const float* __restrict__ w_out,
                const float* __restrict__ b_out,
                float* __restrict__ out)
{
    __shared__ __align__(16) float y_s[2][NN];   // [buf][neuron]
    __shared__ float u_s[2][NII];                // [buf][input]

    const int tid = threadIdx.x;
    const int b   = blockIdx.x;                  // one sequence per CTA
    const bool is_neuron = (tid <  NN);
    const bool is_z      = (tid == NN);
    const bool active    = (tid <= NN);
    const int  n = active ? tid : 0;
    const int  uq = tid - 208;                   // u loaders: tid 208..214
    const bool is_u = (uq >= 0 && uq < NII);

    float* __restrict__ yseq = out;
    float* __restrict__ zseq = out + (size_t)BB * TT * NN;
    float* __restrict__ yfin = zseq + (size_t)BB * TT;

    // ---- full W row in registers (200 fp32 = 100 x b64) ----
    u64 w[NN / 2];
    if (active) {
        const float* base = is_z ? w_out : (W_rec + (size_t)n * NN);
        const u64* wp = reinterpret_cast<const u64*>(base);
        #pragma unroll
        for (int m = 0; m < NN / 2; ++m) w[m] = __ldg(&wp[m]);
    }

    float wia[NII];
    float brec = 0.f, bout = 0.f;
    float yold = 0.f, nz = 0.f;
    const float* np = noise + (size_t)b * TT * NN + n;
    float*       yp = yseq  + (size_t)b * TT * NN + n;

    if (is_neuron) {
        #pragma unroll
        for (int i = 0; i < NII; ++i) wia[i] = fabsf(W_in_raw[n * NII + i]);
        brec = b_rec[n];
        yold = y0[(size_t)b * NN + n];
        y_s[0][n] = yold;
        nz = __ldcs(np);
    }
    if (is_z) bout = b_out[0];
    if (is_u) u_s[0][uq] = u_seq[(size_t)b * TT * NII + uq];
    __syncthreads();

    int buf = 0;
    for (int t = 0; t < TT; ++t) {
        // ---- prefetch next step's noise / u ----
        float nzn = 0.f, un = 0.f;
        if (is_neuron && (t + 1 < TT)) {
            np += NN;
            nzn = __ldcs(np);
        }
        if (is_u && (t + 1 < TT))
            un = __ldcs(&u_seq[((size_t)b * TT + (t + 1)) * NII + uq]);

        if (active) {
            // ---- dot: 50 broadcast LDS.128, 100 FFMA2, 4 independent chains
            const ulonglong2* Y = reinterpret_cast<const ulonglong2*>(y_s[buf]);
            u64 ca = 0ull, cb = 0ull, cc = 0ull, cd = 0ull;
            #pragma unroll
            for (int m = 0; m < NN / 8; ++m) {        // 25 iters x 8 floats
                ulonglong2 p = Y[2 * m];
                ulonglong2 q = Y[2 * m + 1];
                ffma2(ca, w[4 * m + 0], p.x);
                ffma2(cb, w[4 * m + 1], p.y);
                ffma2(cc, w[4 * m + 2], q.x);
                ffma2(cd, w[4 * m + 3], q.y);
            }
            float pre = hsum8(ca, cb, cc, cd);

            if (is_neuron) {
                float dr = brec;
                #pragma unroll
                for (int i = 0; i < NII; ++i)
                    dr = fmaf(wia[i], u_s[buf][i], dr);
                float r  = fmaxf(pre + dr, 0.f);
                float yn = fmaf(OMA_F, yold, fmaf(ALPHA_F, r, NSC_F * nz));
                y_s[buf ^ 1][n] = yn;
                __stcs(yp, yn);
                yp += NN;
                yold = yn;
                nz = nzn;
            } else if (t >= 1) {
                // z thread's dot was over y_{t-1}
                zseq[(size_t)b * TT + (t - 1)] = 1.f / (1.f + expf(-(pre + bout)));
            }
        }
        if (is_u && (t + 1 < TT)) u_s[buf ^ 1][uq] = un;
        __syncthreads();
        buf ^= 1;
    }

    // ---- tails ----
    if (is_neuron)
        yfin[(size_t)b * NN + n] = yold;
    if (is_z) {
        // final readout over y_{T-1} (now in y_s[buf])
        const ulonglong2* Y = reinterpret_cast<const ulonglong2*>(y_s[buf]);
        u64 ca = 0ull, cb = 0ull, cc = 0ull, cd = 0ull;
        #pragma unroll
        for (int m = 0; m < NN / 8; ++m) {
            ulonglong2 p = Y[2 * m];
            ulonglong2 q = Y[2 * m + 1];
            ffma2(ca, w[4 * m + 0], p.x);
            ffma2(cb, w[4 * m + 1], p.y);
            ffma2(cc, w[4 * m + 2], q.x);
            ffma2(cd, w[4 * m + 3], q.y);
        }
        float pre = hsum8(ca, cb, cc, cd);
        zseq[(size_t)b * TT + (TT - 1)] = 1.f / (1.f + expf(-(pre + bout)));
    }
}

extern "C" void kernel_launch(void* const* d_in, const int* in_sizes, int n_in,
                              void* d_out, int out_size) {
    const float* y0       = (const float*)d_in[0];
    const float* u_seq    = (const float*)d_in[1];
    const float* noise    = (const float*)d_in[2];
    const float* W_in_raw = (const float*)d_in[3];
    const float* W_rec    = (const float*)d_in[4];
    const float* b_rec    = (const float*)d_in[5];
    const float* w_out    = (const float*)d_in[6];
    const float* b_out    = (const float*)d_in[7];
    float* out = (float*)d_out;

    rnn_1row_kernel<<<BB, 256>>>(y0, u_seq, noise, W_in_raw, W_rec,
                                 b_rec, w_out, b_out, out);
}